// round 16
// baseline (speedup 1.0000x reference)
#include <cuda_runtime.h>
#include <cuda_fp16.h>
#include <math.h>
#include <stdint.h>

#define CB   16
#define CTE  128
#define CTD  128
#define CE   512
#define CH   512
#define CD   1024
#define CV   32000

// ---- fp32 scratch layout ----
#define OFF_XGF  ((size_t)0)
#define SZ_XGF   ((size_t)CB*CTE*4*CH)
#define OFF_XGB  (OFF_XGF + SZ_XGF)
#define SZ_XGB   ((size_t)CB*CTE*4*CH)
#define OFF_XGD  (OFF_XGB + SZ_XGB)
#define SZ_XGD   ((size_t)CB*CTD*4*CD)
#define OFF_DEC  (OFF_XGD + SZ_XGD)
#define SZ_DEC   ((size_t)CB*CTD*CD)
#define OFF_Q    (OFF_DEC + SZ_DEC)
#define SZ_Q     ((size_t)CB*CTD*CD)
#define OFF_K    (OFF_Q + SZ_Q)
#define SZ_K     ((size_t)CB*CTE*CD)
#define OFF_V    (OFF_K + SZ_K)
#define SZ_V     ((size_t)CB*CTE*CD)
#define OFF_CTX  (OFF_V + SZ_V)
#define SZ_CTX   ((size_t)CB*CTD*CD)
#define OFF_HE   (OFF_CTX + SZ_CTX)
#define SZ_HE    ((size_t)2*2*CH*CB)
#define OFF_HD   (OFF_HE + SZ_HE)
#define SZ_HD    ((size_t)2*CD*CB)
#define OFF_CDI  (OFF_HD + SZ_HD)
#define SZ_CDI   ((size_t)CD*CB)
#define SCRATCH_TOTAL (OFF_CDI + SZ_CDI)

// ---- fp16 scratch layout ----
#define HOFF_WIHF ((size_t)0)
#define HSZ_WIHF  ((size_t)4*CH*CE)
#define HOFF_WIHB (HOFF_WIHF + HSZ_WIHF)
#define HSZ_WIHB  ((size_t)4*CH*CE)
#define HOFF_WIHD (HOFF_WIHB + HSZ_WIHB)
#define HSZ_WIHD  ((size_t)4*CD*CE)
#define HOFF_WQ   (HOFF_WIHD + HSZ_WIHD)
#define HSZ_WQ    ((size_t)CD*CD)
#define HOFF_WK   (HOFF_WQ + HSZ_WQ)
#define HSZ_WK    ((size_t)CD*CD)
#define HOFF_WV   (HOFF_WK + HSZ_WK)
#define HSZ_WV    ((size_t)CD*CD)
#define HOFF_WFC  (HOFF_WV + HSZ_WV)
#define HSZ_WFC   ((size_t)CV*CD)
#define HOFF_XE   (HOFF_WFC + HSZ_WFC)
#define HSZ_XE    ((size_t)CB*CTE*CE)
#define HOFF_XD   (HOFF_XE + HSZ_XE)
#define HSZ_XD    ((size_t)CB*CTD*CE)
#define HOFF_DEC  (HOFF_XD + HSZ_XD)
#define HSZ_DEC   ((size_t)CB*CTD*CD)
#define HOFF_ENC  (HOFF_DEC + HSZ_DEC)
#define HSZ_ENC   ((size_t)CB*CTE*CD)
#define HOFF_LN   (HOFF_ENC + HSZ_ENC)
#define HSZ_LN    ((size_t)CB*CTD*CD)
#define HSCRATCH_TOTAL (HOFF_LN + HSZ_LN)

__device__ float  g_scratch[SCRATCH_TOTAL];
__device__ __half g_scratch_h[HSCRATCH_TOTAL];
__device__ unsigned g_flags[128 * 32];   // flag i lives at g_flags[i*32] (own 128B line)
__device__ unsigned g_rel2;

__device__ __forceinline__ unsigned ld_acq_gpu(const unsigned* p) {
    unsigned v;
    asm volatile("ld.acquire.gpu.global.b32 %0, [%1];" : "=r"(v) : "l"(p) : "memory");
    return v;
}
__device__ __forceinline__ void st_rel_gpu(unsigned* p, unsigned v) {
    asm volatile("st.release.gpu.global.b32 [%0], %1;" :: "l"(p), "r"(v) : "memory");
}

// Distributed-flag grid barrier: per-CTA flag (no atomic contention), CTA0
// gathers via 127 parallel polls, then releases one counter. Generations are
// monotonic across launches/replays; base read from g_rel2 at kernel entry.
__device__ __forceinline__ void grid_sync2(unsigned gen) {
    __syncthreads();
    if (blockIdx.x == 0) {
        unsigned t = threadIdx.x;
        if (t > 0 && t < 128) {
            while (ld_acq_gpu(&g_flags[t * 32]) != gen) {}
        }
        __syncthreads();
        if (threadIdx.x == 0) st_rel_gpu(&g_rel2, gen);
    } else {
        if (threadIdx.x == 0) {
            st_rel_gpu(&g_flags[blockIdx.x * 32], gen);
            while (ld_acq_gpu(&g_rel2) != gen) {}
        }
        __syncthreads();
    }
}

__device__ __forceinline__ float sigmoidf_(float x) { return 1.0f / (1.0f + expf(-x)); }

__device__ __forceinline__ uint32_t smem_u32(const void* p) {
    uint32_t a;
    asm("{ .reg .u64 t; cvta.to.shared.u64 t, %1; cvt.u32.u64 %0, t; }" : "=r"(a) : "l"(p));
    return a;
}
__device__ __forceinline__ void cp_async16(uint32_t dst, const void* src) {
    asm volatile("cp.async.cg.shared.global [%0], [%1], 16;" :: "r"(dst), "l"(src));
}
__device__ __forceinline__ void cp_commit() { asm volatile("cp.async.commit_group;" ::: "memory"); }

// ---- packed f32x2 helpers ----
__device__ __forceinline__ uint64_t pack2(float lo, float hi) {
    uint64_t r;
    asm("mov.b64 %0, {%1,%2};" : "=l"(r) : "f"(lo), "f"(hi));
    return r;
}
__device__ __forceinline__ void unpack2(uint64_t v, float& lo, float& hi) {
    asm("mov.b64 {%0,%1}, %2;" : "=f"(lo), "=f"(hi) : "l"(v));
}
__device__ __forceinline__ void fma2(uint64_t& acc, uint64_t a, uint64_t b) {
    asm("fma.rn.f32x2 %0, %1, %2, %0;" : "+l"(acc) : "l"(a), "l"(b));
}
__device__ __forceinline__ void add2(uint64_t& a, uint64_t b) {
    asm("add.rn.f32x2 %0, %0, %1;" : "+l"(a) : "l"(b));
}

__device__ __forceinline__ void mma_f16(float* c, const uint32_t* a, const uint32_t* b) {
    asm volatile(
        "mma.sync.aligned.m16n8k16.row.col.f32.f16.f16.f32 "
        "{%0,%1,%2,%3}, {%4,%5,%6,%7}, {%8,%9}, {%0,%1,%2,%3};"
        : "+f"(c[0]), "+f"(c[1]), "+f"(c[2]), "+f"(c[3])
        : "r"(a[0]), "r"(a[1]), "r"(a[2]), "r"(a[3]), "r"(b[0]), "r"(b[1]));
}
__device__ __forceinline__ uint32_t h2_bits(float lo, float hi) {
    __half2 h = __floats2half2_rn(lo, hi);
    return *(uint32_t*)&h;
}

// ---- fp32 -> fp16 array convert ----
__global__ void __launch_bounds__(256) cvt_fp16_kernel(
    const float* __restrict__ src, __half* __restrict__ dst)
{
    int i = blockIdx.x * 256 + threadIdx.x;
    float4 v = ((const float4*)src)[i];
    uint2 u = make_uint2(h2_bits(v.x, v.y), h2_bits(v.z, v.w));
    *(uint2*)(dst + (size_t)i * 4) = u;
}

// ===================== fp16 m16n8k16 GEMM, cp.async 3-stage =====================
#define BM 128
#define BN 128
#define GBK 32
#define GST 3
#define PADH 40
#define TILE_HH (128 * PADH)
#define GEMM_SMEM (GST * 2 * TILE_HH * 2)    // 61440 B

__global__ void __launch_bounds__(256, 2) gemm_tc_kernel(
    const __half* __restrict__ A, const __half* __restrict__ W,
    const float* __restrict__ bias1, const float* __restrict__ bias2,
    float* __restrict__ C, int N, int K)
{
    extern __shared__ __half hsm_g[];
    __half* sA = hsm_g;
    __half* sB = hsm_g + GST * TILE_HH;

    const int tid  = threadIdx.x;
    const int warp = tid >> 5;
    const int lane = tid & 31;
    const int g    = lane >> 2;
    const int tig  = lane & 3;
    const int wm   = warp >> 2;
    const int wn   = warp & 3;
    const int m0   = blockIdx.x * BM;
    const int n0   = blockIdx.y * BN;
    const int nst  = K / GBK;

    const uint32_t sA_u = smem_u32(sA);
    const uint32_t sB_u = smem_u32(sB);

    float acc[4][4][4];
#pragma unroll
    for (int i = 0; i < 4; i++)
#pragma unroll
        for (int j = 0; j < 4; j++)
#pragma unroll
            for (int r = 0; r < 4; r++) acc[i][j][r] = 0.0f;

    auto load_stage = [&](int kidx, int s) {
        const __half* Ag = A + (size_t)m0 * K + kidx * GBK;
        const __half* Wg = W + (size_t)n0 * K + kidx * GBK;
        uint32_t aB = sA_u + (uint32_t)(s * TILE_HH * 2);
        uint32_t bB = sB_u + (uint32_t)(s * TILE_HH * 2);
#pragma unroll
        for (int q = 0; q < 2; q++) {
            int ch = q * 256 + tid;
            int r = ch >> 2, c = ch & 3;
            cp_async16(aB + (uint32_t)(r * 80 + c * 16), Ag + (size_t)r * K + c * 8);
        }
#pragma unroll
        for (int q = 0; q < 2; q++) {
            int ch = q * 256 + tid;
            int r = ch >> 2, c = ch & 3;
            cp_async16(bB + (uint32_t)(r * 80 + c * 16), Wg + (size_t)r * K + c * 8);
        }
        cp_commit();
    };

    load_stage(0, 0);
    load_stage(1, 1);

    for (int i = 0; i < nst; i++) {
        if (i + 2 < nst) {
            load_stage(i + 2, (i + 2) % GST);
            asm volatile("cp.async.wait_group 2;" ::: "memory");
        } else if (i + 1 < nst) {
            asm volatile("cp.async.wait_group 1;" ::: "memory");
        } else {
            asm volatile("cp.async.wait_group 0;" ::: "memory");
        }
        __syncthreads();

        const int s = i % GST;
        const uint32_t* aS = (const uint32_t*)(sA + s * TILE_HH);
        const uint32_t* bS = (const uint32_t*)(sB + s * TILE_HH);

#pragma unroll
        for (int ks = 0; ks < 2; ks++) {
            const int u0 = ks * 8 + tig;
            uint32_t af[4][4], bf[4][2];
#pragma unroll
            for (int mt = 0; mt < 4; mt++) {
                int row = wm * 64 + mt * 16 + g;
                af[mt][0] = aS[row * 20 + u0];
                af[mt][1] = aS[(row + 8) * 20 + u0];
                af[mt][2] = aS[row * 20 + u0 + 4];
                af[mt][3] = aS[(row + 8) * 20 + u0 + 4];
            }
#pragma unroll
            for (int nt = 0; nt < 4; nt++) {
                int n = wn * 32 + nt * 8 + g;
                bf[nt][0] = bS[n * 20 + u0];
                bf[nt][1] = bS[n * 20 + u0 + 4];
            }
#pragma unroll
            for (int mt = 0; mt < 4; mt++)
#pragma unroll
                for (int nt = 0; nt < 4; nt++)
                    mma_f16(acc[mt][nt], af[mt], bf[nt]);
        }
        __syncthreads();
    }

#pragma unroll
    for (int nt = 0; nt < 4; nt++) {
        int cn = n0 + wn * 32 + nt * 8 + 2 * tig;
        float b0 = bias1 ? bias1[cn] : 0.0f;
        float b1 = bias1 ? bias1[cn + 1] : 0.0f;
        if (bias2) { b0 += bias2[cn]; b1 += bias2[cn + 1]; }
#pragma unroll
        for (int mt = 0; mt < 4; mt++) {
            int r = m0 + wm * 64 + mt * 16 + g;
            float2 o0 = make_float2(acc[mt][nt][0] + b0, acc[mt][nt][1] + b1);
            float2 o1 = make_float2(acc[mt][nt][2] + b0, acc[mt][nt][3] + b1);
            *(float2*)(C + (size_t)r * N + cn) = o0;
            *(float2*)(C + (size_t)(r + 8) * N + cn) = o1;
        }
    }
}

// ---- embedding gather -> fp16 ----
__global__ void __launch_bounds__(128) embed_kernel(
    const int* __restrict__ eseq, const int* __restrict__ dseq,
    const float* __restrict__ eemb, const float* __restrict__ demb,
    __half* __restrict__ xe, __half* __restrict__ xd)
{
    int r = blockIdx.x;
    int tid = threadIdx.x;
    if (r < CB * CTE) {
        int tok = eseq[r];
        float4 v = ((const float4*)(eemb + (size_t)tok * CE))[tid];
        ((uint2*)(xe + (size_t)r * CE))[tid] = make_uint2(h2_bits(v.x, v.y), h2_bits(v.z, v.w));
    } else {
        int r2 = r - CB * CTE;
        int tok = dseq[r2];
        float4 v = ((const float4*)(demb + (size_t)tok * CE))[tid];
        ((uint2*)(xd + (size_t)r2 * CE))[tid] = make_uint2(h2_bits(v.x, v.y), h2_bits(v.z, v.w));
    }
}

// ===================== encoder recurrence (1024 thr, k-pair scheme) =====================
#define EW_STRIDE (4 * CH + 4)
#define HPAD_E    (CH + 4)
#define ENC_RED_F (8 * EW_STRIDE + CB * HPAD_E)
#define ENC_SMEM  (ENC_RED_F * 4 + 7 * 8 * 16 * 16)

__global__ void __launch_bounds__(1024) enc_rnn_kernel(
    const float* __restrict__ Whh_f, const float* __restrict__ Whh_b,
    const float* __restrict__ xgf, const float* __restrict__ xgb,
    __half* __restrict__ ench, float* __restrict__ hebuf,
    float* __restrict__ hd0, float* __restrict__ cdi)
{
    extern __shared__ float sm[];
    float* wsm = sm;
    float* hsm = sm + 8 * EW_STRIDE;
    ulonglong2* red = (ulonglong2*)(sm + ENC_RED_F);
    __shared__ unsigned s_base;

    const int tid = threadIdx.x;
    const int b = tid & 15, ul = (tid >> 4) & 7, qr = tid >> 7;
    const int dir = blockIdx.x >> 6;
    const int u = (blockIdx.x & 63) * 8 + ul;
    const int ubase = (blockIdx.x & 63) * 8;

    const float* Whh = dir ? Whh_b : Whh_f;
    const float* xg  = dir ? xgb : xgf;

    if (tid == 0) s_base = ld_acq_gpu(&g_rel2);

    for (int i = tid; i < 4096; i += 1024) {
        int ulw = i >> 9;
        int g = (i >> 7) & 3;
        int k4 = i & 127;
        float4 v = *(const float4*)(Whh + ((size_t)(g * CH + ubase + ulw)) * CH + k4 * 4);
        float* dst = wsm + ulw * EW_STRIDE + k4 * 16 + ((g & 2) << 1) + ((g & 1) << 1);
        dst[0] = v.x; dst[1] = v.y; dst[8] = v.z; dst[9] = v.w;
    }

    const ulonglong2* wq = (const ulonglong2*)(wsm + ul * EW_STRIDE) + qr * 64;
    const ulonglong2* hq = (const ulonglong2*)(hsm + b * HPAD_E) + qr * 16;

    float c = 0.0f, h = 0.0f;
    if (qr == 0)
        __stcg(&hebuf[((size_t)(0 * 2 + dir) * CB + b) * CH + u], 0.0f);
    __syncthreads();
    unsigned gen = s_base;
    grid_sync2(++gen);

    for (int t = 0; t < CTE; t++) {
        const int cur = t & 1;
        {
            const float4* src = (const float4*)(hebuf + (size_t)(cur * 2 + dir) * (CB * CH));
            for (int i = tid; i < CB * CH / 4; i += 1024) {
                int bb = i >> 7, k4 = i & 127;
                *(float4*)(hsm + bb * HPAD_E + k4 * 4) = __ldcg(&src[i]);
            }
        }
        __syncthreads();

        const int te = dir ? (CTE - 1 - t) : t;
        float xgi = 0, xgf2 = 0, xgg = 0, xgo = 0;
        if (qr == 0) {
            size_t xb = ((size_t)(b * CTE + te)) * (4 * CH) + u;
            xgi = xg[xb]; xgf2 = xg[xb + CH];
            xgg = xg[xb + 2 * CH]; xgo = xg[xb + 3 * CH];
        }

        uint64_t ai = 0, af = 0, ag = 0, ao = 0;
#pragma unroll 4
        for (int k4 = 0; k4 < 16; k4++) {
            ulonglong2 hh = hq[k4];
            ulonglong2 w0 = wq[k4 * 4 + 0];
            ulonglong2 w1 = wq[k4 * 4 + 1];
            ulonglong2 w2 = wq[k4 * 4 + 2];
            ulonglong2 w3 = wq[k4 * 4 + 3];
            fma2(ai, w0.x, hh.x); fma2(af, w0.y, hh.x);
            fma2(ag, w1.x, hh.x); fma2(ao, w1.y, hh.x);
            fma2(ai, w2.x, hh.y); fma2(af, w2.y, hh.y);
            fma2(ag, w3.x, hh.y); fma2(ao, w3.y, hh.y);
        }
        float ai_l, ai_h, af_l, af_h, ag_l, ag_h, ao_l, ao_h;
        unpack2(ai, ai_l, ai_h); unpack2(af, af_l, af_h);
        unpack2(ag, ag_l, ag_h); unpack2(ao, ao_l, ao_h);
        float si = ai_l + ai_h, sf = af_l + af_h;
        float sg = ag_l + ag_h, so = ao_l + ao_h;

        if (qr) {
            ulonglong2 r; r.x = pack2(si, sf); r.y = pack2(sg, so);
            red[((qr - 1) * 8 + ul) * 16 + b] = r;
        }
        __syncthreads();
        if (qr == 0) {
            uint64_t p0 = pack2(si + xgi, sf + xgf2);
            uint64_t p1 = pack2(sg + xgg, so + xgo);
#pragma unroll
            for (int q = 0; q < 7; q++) {
                ulonglong2 r = red[(q * 8 + ul) * 16 + b];
                add2(p0, r.x);
                add2(p1, r.y);
            }
            float vi, vf, vg, vo;
            unpack2(p0, vi, vf);
            unpack2(p1, vg, vo);
            float ig = sigmoidf_(vi), fg = sigmoidf_(vf);
            float gg = tanhf(vg),     og = sigmoidf_(vo);
            c = fg * c + ig * gg;
            h = og * tanhf(c);

            __stcg(&hebuf[((size_t)((cur ^ 1) * 2 + dir) * CB + b) * CH + u], h);
            ench[((size_t)(b * CTE + te)) * CD + dir * CH + u] = __float2half(h);
        }
        grid_sync2(++gen);
    }

    if (qr == 0) {
        __stcg(&hd0[(size_t)b * CD + dir * CH + u], h);
        __stcg(&cdi[(size_t)b * CD + dir * CH + u], c);
    }
}

// ===================== decoder recurrence (1024 thr, k-pair scheme) =====================
#define DW_STRIDE (4 * CD + 4)
#define HPAD_D    (CD + 4)
#define DEC_RED_F (8 * DW_STRIDE + CB * HPAD_D)
#define DEC_SMEM  (DEC_RED_F * 4 + 7 * 8 * 16 * 16)

__global__ void __launch_bounds__(1024) dec_rnn_kernel(
    const float* __restrict__ Whh, const float* __restrict__ xg,
    float* __restrict__ dec, __half* __restrict__ dech,
    float* __restrict__ hbuf, const float* __restrict__ cinit)
{
    extern __shared__ float sm[];
    float* wsm = sm;
    float* hsm = sm + 8 * DW_STRIDE;
    ulonglong2* red = (ulonglong2*)(sm + DEC_RED_F);
    __shared__ unsigned s_base;

    const int tid = threadIdx.x;
    const int b = tid & 15, ul = (tid >> 4) & 7, qr = tid >> 7;
    const int u = blockIdx.x * 8 + ul;
    const int ubase = blockIdx.x * 8;

    if (tid == 0) s_base = ld_acq_gpu(&g_rel2);

    for (int i = tid; i < 8192; i += 1024) {
        int ulw = i >> 10;
        int g = (i >> 8) & 3;
        int k4 = i & 255;
        float4 v = *(const float4*)(Whh + ((size_t)(g * CD + ubase + ulw)) * CD + k4 * 4);
        float* dst = wsm + ulw * DW_STRIDE + k4 * 16 + ((g & 2) << 1) + ((g & 1) << 1);
        dst[0] = v.x; dst[1] = v.y; dst[8] = v.z; dst[9] = v.w;
    }

    const ulonglong2* wq = (const ulonglong2*)(wsm + ul * DW_STRIDE) + qr * 128;
    const ulonglong2* hq = (const ulonglong2*)(hsm + b * HPAD_D) + qr * 32;

    float c = (qr == 0) ? __ldcg(&cinit[(size_t)b * CD + u]) : 0.0f;
    __syncthreads();
    unsigned gen = s_base;

    for (int t = 0; t < CTD; t++) {
        const int cur = t & 1;
        {
            const float4* src = (const float4*)(hbuf + (size_t)cur * (CB * CD));
            for (int i = tid; i < CB * CD / 4; i += 1024) {
                int bb = i >> 8, k4 = i & 255;
                *(float4*)(hsm + bb * HPAD_D + k4 * 4) = __ldcg(&src[i]);
            }
        }
        __syncthreads();

        float xgi = 0, xgf2 = 0, xgg = 0, xgo = 0;
        if (qr == 0) {
            size_t xb = ((size_t)(b * CTD + t)) * (4 * CD) + u;
            xgi = xg[xb]; xgf2 = xg[xb + CD];
            xgg = xg[xb + 2 * CD]; xgo = xg[xb + 3 * CD];
        }

        uint64_t ai = 0, af = 0, ag = 0, ao = 0;
#pragma unroll 4
        for (int k4 = 0; k4 < 32; k4++) {
            ulonglong2 hh = hq[k4];
            ulonglong2 w0 = wq[k4 * 4 + 0];
            ulonglong2 w1 = wq[k4 * 4 + 1];
            ulonglong2 w2 = wq[k4 * 4 + 2];
            ulonglong2 w3 = wq[k4 * 4 + 3];
            fma2(ai, w0.x, hh.x); fma2(af, w0.y, hh.x);
            fma2(ag, w1.x, hh.x); fma2(ao, w1.y, hh.x);
            fma2(ai, w2.x, hh.y); fma2(af, w2.y, hh.y);
            fma2(ag, w3.x, hh.y); fma2(ao, w3.y, hh.y);
        }
        float ai_l, ai_h, af_l, af_h, ag_l, ag_h, ao_l, ao_h;
        unpack2(ai, ai_l, ai_h); unpack2(af, af_l, af_h);
        unpack2(ag, ag_l, ag_h); unpack2(ao, ao_l, ao_h);
        float si = ai_l + ai_h, sf = af_l + af_h;
        float sg = ag_l + ag_h, so = ao_l + ao_h;

        if (qr) {
            ulonglong2 r; r.x = pack2(si, sf); r.y = pack2(sg, so);
            red[((qr - 1) * 8 + ul) * 16 + b] = r;
        }
        __syncthreads();
        if (qr == 0) {
            uint64_t p0 = pack2(si + xgi, sf + xgf2);
            uint64_t p1 = pack2(sg + xgg, so + xgo);
#pragma unroll
            for (int q = 0; q < 7; q++) {
                ulonglong2 r = red[(q * 8 + ul) * 16 + b];
                add2(p0, r.x);
                add2(p1, r.y);
            }
            float vi, vf, vg, vo;
            unpack2(p0, vi, vf);
            unpack2(p1, vg, vo);
            float ig = sigmoidf_(vi), fg = sigmoidf_(vf);
            float gg = tanhf(vg),     og = sigmoidf_(vo);
            c = fg * c + ig * gg;
            float h = og * tanhf(c);

            __stcg(&hbuf[(size_t)(cur ^ 1) * (CB * CD) + (size_t)b * CD + u], h);
            dec[((size_t)(b * CTD + t)) * CD + u] = h;
            dech[((size_t)(b * CTD + t)) * CD + u] = __float2half(h);
        }
        grid_sync2(++gen);
    }
}

// ===================== attention v2: block per (b, 16-query group) =====================
#define ATTN_SMEM ((16 * 1024 + 16 * 132 + 16 * 1024) * 4)

__global__ void __launch_bounds__(256) attn_kernel(
    const int* __restrict__ eseq,
    const float* __restrict__ q, const float* __restrict__ k,
    const float* __restrict__ v, float* __restrict__ ctx)
{
    extern __shared__ float asmem[];
    float* qs  = asmem;
    float* att = qs + 16 * 1024;
    float* vs  = att + 16 * 132;

    const int tid = threadIdx.x;
    const int b   = blockIdx.x >> 3;
    const int qt0 = (blockIdx.x & 7) * 16;

    for (int i = tid; i < 4096; i += 256) {
        int row = i >> 8, c = i & 255;
        ((float4*)(qs + row * 1024))[c] =
            ((const float4*)(q + ((size_t)(b * CTD + qt0 + row)) * CD))[c];
    }
    __syncthreads();

    {
        const int qh = tid >> 7, kt = tid & 127;
        float s[8] = {0, 0, 0, 0, 0, 0, 0, 0};
        const float4* kr = (const float4*)(k + ((size_t)(b * CTE + kt)) * CD);
#pragma unroll 4
        for (int k4 = 0; k4 < 256; k4++) {
            float4 kv = kr[k4];
#pragma unroll
            for (int j = 0; j < 8; j++) {
                float4 q4 = ((const float4*)(qs + (qh * 8 + j) * 1024))[k4];
                s[j] = fmaf(q4.x, kv.x, s[j]);
                s[j] = fmaf(q4.y, kv.y, s[j]);
                s[j] = fmaf(q4.z, kv.z, s[j]);
                s[j] = fmaf(q4.w, kv.w, s[j]);
            }
        }
        bool pad = (eseq[b * CTE + kt] == 0);
#pragma unroll
        for (int j = 0; j < 8; j++)
            att[(qh * 8 + j) * 132 + kt] = pad ? -1e30f : s[j] * 0.03125f;
    }
    __syncthreads();

    {
        const int w = tid >> 5, lane = tid & 31;
#pragma unroll
        for (int rr = 0; rr < 2; rr++) {
            int r = w * 2 + rr;
            float m = -1e30f;
#pragma unroll
            for (int c = lane; c < 128; c += 32) m = fmaxf(m, att[r * 132 + c]);
#pragma unroll
            for (int o = 16; o > 0; o >>= 1) m = fmaxf(m, __shfl_xor_sync(0xffffffffu, m, o));
            float sum = 0.0f;
#pragma unroll
            for (int c = lane; c < 128; c += 32) {
                float e = expf(att[r * 132 + c] - m);
                att[r * 132 + c] = e;
                sum += e;
            }
#pragma unroll
            for (int o = 16; o > 0; o >>= 1) sum += __shfl_xor_sync(0xffffffffu, sum, o);
            float inv = 1.0f / sum;
#pragma unroll
            for (int c = lane; c < 128; c += 32) att[r * 132 + c] *= inv;
        }
    }
    __syncthreads();

    {
        const int qt_l = tid >> 4, ds = tid & 15;
        float4 acc[16];
#pragma unroll
        for (int j = 0; j < 16; j++) acc[j] = make_float4(0, 0, 0, 0);

        for (int chunk = 0; chunk < 8; chunk++) {
            for (int i = tid; i < 4096; i += 256) {
                int row = i >> 8, c = i & 255;
                ((float4*)(vs + row * 1024))[c] =
                    ((const float4*)(v + ((size_t)(b * CTE + chunk * 16 + row)) * CD))[c];
            }
            __syncthreads();
#pragma unroll 2
            for (int r = 0; r < 16; r++) {
                float a = att[qt_l * 132 + chunk * 16 + r];
                const float4* vr = (const float4*)(vs + r * 1024) + ds;
#pragma unroll
                for (int j = 0; j < 16; j++) {
                    float4 vv = vr[j * 16];
                    acc[j].x = fmaf(a, vv.x, acc[j].x);
                    acc[j].y = fmaf(a, vv.y, acc[j].y);
                    acc[j].z = fmaf(a, vv.z, acc[j].z);
                    acc[j].w = fmaf(a, vv.w, acc[j].w);
                }
            }
            __syncthreads();
        }

        float4* cr = (float4*)(ctx + ((size_t)(b * CTD + qt0 + qt_l)) * CD) + ds;
#pragma unroll
        for (int j = 0; j < 16; j++) cr[j * 16] = acc[j];
    }
}

// ---- tanh(dec + ctx) -> layernorm -> fp16 ----
__global__ void __launch_bounds__(256) tanh_ln_kernel(
    const float* __restrict__ dec, const float* __restrict__ ctx,
    const float* __restrict__ gamma, const float* __restrict__ beta,
    __half* __restrict__ lnh)
{
    __shared__ float rs[8], rss[8];
    const int tid = threadIdx.x;
    const int row = blockIdx.x;
    const float4 a = ((const float4*)(dec + (size_t)row * CD))[tid];
    const float4 b = ((const float4*)(ctx + (size_t)row * CD))[tid];
    float t0 = tanhf(a.x + b.x), t1 = tanhf(a.y + b.y);
    float t2 = tanhf(a.z + b.z), t3 = tanhf(a.w + b.w);
    float s = t0 + t1 + t2 + t3;
    float ss = t0*t0 + t1*t1 + t2*t2 + t3*t3;
#pragma unroll
    for (int o = 16; o > 0; o >>= 1) {
        s  += __shfl_xor_sync(0xffffffffu, s, o);
        ss += __shfl_xor_sync(0xffffffffu, ss, o);
    }
    if ((tid & 31) == 0) { rs[tid >> 5] = s; rss[tid >> 5] = ss; }
    __syncthreads();
    if (tid < 8) { s = rs[tid]; ss = rss[tid]; }
    else { s = 0; ss = 0; }
    if (tid < 32) {
#pragma unroll
        for (int o = 4; o > 0; o >>= 1) {
            s  += __shfl_xor_sync(0xffffffffu, s, o);
            ss += __shfl_xor_sync(0xffffffffu, ss, o);
        }
        if (tid == 0) { rs[0] = s; rss[0] = ss; }
    }
    __syncthreads();
    float mu = rs[0] * (1.0f / CD);
    float var = rss[0] * (1.0f / CD) - mu * mu;
    float rstd = rsqrtf(var + 1e-5f);
    const float4 g = ((const float4*)gamma)[tid];
    const float4 be = ((const float4*)beta)[tid];
    float o0 = (t0 - mu) * rstd * g.x + be.x;
    float o1 = (t1 - mu) * rstd * g.y + be.y;
    float o2 = (t2 - mu) * rstd * g.z + be.z;
    float o3 = (t3 - mu) * rstd * g.w + be.w;
    ((uint2*)(lnh + (size_t)row * CD))[tid] = make_uint2(h2_bits(o0, o1), h2_bits(o2, o3));
}

extern "C" void kernel_launch(void* const* d_in, const int* in_sizes, int n_in,
                              void* d_out, int out_size) {
    const int*   eseq  = (const int*)d_in[0];
    const int*   dseq  = (const int*)d_in[1];
    const float* eemb  = (const float*)d_in[2];
    const float* demb  = (const float*)d_in[3];
    const float* Wih_f = (const float*)d_in[4];
    const float* Whh_f = (const float*)d_in[5];
    const float* bih_f = (const float*)d_in[6];
    const float* bhh_f = (const float*)d_in[7];
    const float* Wih_b = (const float*)d_in[8];
    const float* Whh_b = (const float*)d_in[9];
    const float* bih_b = (const float*)d_in[10];
    const float* bhh_b = (const float*)d_in[11];
    const float* Wih_d = (const float*)d_in[12];
    const float* Whh_d = (const float*)d_in[13];
    const float* bih_d = (const float*)d_in[14];
    const float* bhh_d = (const float*)d_in[15];
    const float* Wq = (const float*)d_in[16];
    const float* bq = (const float*)d_in[17];
    const float* Wk = (const float*)d_in[18];
    const float* bk = (const float*)d_in[19];
    const float* Wv = (const float*)d_in[20];
    const float* bv = (const float*)d_in[21];
    const float* Wfc = (const float*)d_in[22];
    const float* bfc = (const float*)d_in[23];
    const float* gamma = (const float*)d_in[24];
    const float* beta  = (const float*)d_in[25];
    float* out = (float*)d_out;

    float* S = nullptr;
    cudaGetSymbolAddress((void**)&S, g_scratch);
    __half* H = nullptr;
    cudaGetSymbolAddress((void**)&H, g_scratch_h);

    float* xgf = S + OFF_XGF;
    float* xgb = S + OFF_XGB;
    float* xgd = S + OFF_XGD;
    float* dec = S + OFF_DEC;
    float* q   = S + OFF_Q;
    float* k   = S + OFF_K;
    float* v   = S + OFF_V;
    float* ctx = S + OFF_CTX;
    float* heb = S + OFF_HE;
    float* hdb = S + OFF_HD;
    float* cdi = S + OFF_CDI;

    __half* wihf_h = H + HOFF_WIHF;
    __half* wihb_h = H + HOFF_WIHB;
    __half* wihd_h = H + HOFF_WIHD;
    __half* wq_h   = H + HOFF_WQ;
    __half* wk_h   = H + HOFF_WK;
    __half* wv_h   = H + HOFF_WV;
    __half* wfc_h  = H + HOFF_WFC;
    __half* xe_h   = H + HOFF_XE;
    __half* xd_h   = H + HOFF_XD;
    __half* dec_h  = H + HOFF_DEC;
    __half* enc_h  = H + HOFF_ENC;
    __half* ln_h   = H + HOFF_LN;

    cudaFuncSetAttribute(enc_rnn_kernel,
                         cudaFuncAttributeMaxDynamicSharedMemorySize, ENC_SMEM);
    cudaFuncSetAttribute(dec_rnn_kernel,
                         cudaFuncAttributeMaxDynamicSharedMemorySize, DEC_SMEM);
    cudaFuncSetAttribute(gemm_tc_kernel,
                         cudaFuncAttributeMaxDynamicSharedMemorySize, GEMM_SMEM);
    cudaFuncSetAttribute(attn_kernel,
                         cudaFuncAttributeMaxDynamicSharedMemorySize, ATTN_SMEM);

    const int M = CB * CTE;  // 2048 (== CB*CTD)

    embed_kernel<<<CB * CTE + CB * CTD, 128>>>(eseq, dseq, eemb, demb, xe_h, xd_h);
    cvt_fp16_kernel<<<(int)(HSZ_WIHF/1024), 256>>>(Wih_f, wihf_h);
    cvt_fp16_kernel<<<(int)(HSZ_WIHB/1024), 256>>>(Wih_b, wihb_h);
    gemm_tc_kernel<<<dim3(M/BM, 4*CH/BN), 256, GEMM_SMEM>>>(xe_h, wihf_h, bih_f, bhh_f, xgf, 4*CH, CE);
    gemm_tc_kernel<<<dim3(M/BM, 4*CH/BN), 256, GEMM_SMEM>>>(xe_h, wihb_h, bih_b, bhh_b, xgb, 4*CH, CE);
    cvt_fp16_kernel<<<(int)(HSZ_WIHD/1024), 256>>>(Wih_d, wihd_h);
    gemm_tc_kernel<<<dim3(M/BM, 4*CD/BN), 256, GEMM_SMEM>>>(xd_h, wihd_h, bih_d, bhh_d, xgd, 4*CD, CE);

    enc_rnn_kernel<<<128, 1024, ENC_SMEM>>>(Whh_f, Whh_b, xgf, xgb, enc_h, heb, hdb, cdi);
    dec_rnn_kernel<<<128, 1024, DEC_SMEM>>>(Whh_d, xgd, dec, dec_h, hdb, cdi);

    cvt_fp16_kernel<<<(int)(HSZ_WQ/1024), 256>>>(Wq, wq_h);
    cvt_fp16_kernel<<<(int)(HSZ_WK/1024), 256>>>(Wk, wk_h);
    cvt_fp16_kernel<<<(int)(HSZ_WV/1024), 256>>>(Wv, wv_h);
    gemm_tc_kernel<<<dim3(M/BM, CD/BN), 256, GEMM_SMEM>>>(dec_h, wq_h, bq, nullptr, q, CD, CD);
    gemm_tc_kernel<<<dim3(M/BM, CD/BN), 256, GEMM_SMEM>>>(enc_h, wk_h, bk, nullptr, k, CD, CD);
    gemm_tc_kernel<<<dim3(M/BM, CD/BN), 256, GEMM_SMEM>>>(enc_h, wv_h, bv, nullptr, v, CD, CD);

    attn_kernel<<<CB * 8, 256, ATTN_SMEM>>>(eseq, q, k, v, ctx);
    tanh_ln_kernel<<<CB * CTD, 256>>>(dec, ctx, gamma, beta, ln_h);

    cvt_fp16_kernel<<<(int)(HSZ_WFC/1024), 256>>>(Wfc, wfc_h);
    gemm_tc_kernel<<<dim3(M/BM, CV/BN), 256, GEMM_SMEM>>>(ln_h, wfc_h, bfc, nullptr, out, CV, CD);
}

// round 17
// speedup vs baseline: 1.0411x; 1.0411x over previous
#include <cuda_runtime.h>
#include <cuda_fp16.h>
#include <math.h>
#include <stdint.h>

#define CB   16
#define CTE  128
#define CTD  128
#define CE   512
#define CH   512
#define CD   1024
#define CV   32000

// ---- fp32 scratch layout ----
#define OFF_XGFB ((size_t)0)
#define SZ_XGFB  ((size_t)CB*CTE*8*CH)        // fused xgf|xgb
#define OFF_XGD  (OFF_XGFB + SZ_XGFB)
#define SZ_XGD   ((size_t)CB*CTD*4*CD)
#define OFF_DEC  (OFF_XGD + SZ_XGD)
#define SZ_DEC   ((size_t)CB*CTD*CD)
#define OFF_Q    (OFF_DEC + SZ_DEC)
#define SZ_Q     ((size_t)CB*CTD*CD)
#define OFF_KV   (OFF_Q + SZ_Q)
#define SZ_KV    ((size_t)CB*CTE*2*CD)        // fused k|v per row
#define OFF_CTX  (OFF_KV + SZ_KV)
#define SZ_CTX   ((size_t)CB*CTD*CD)
#define OFF_HE   (OFF_CTX + SZ_CTX)
#define SZ_HE    ((size_t)2*2*CH*CB)
#define OFF_HD   (OFF_HE + SZ_HE)
#define SZ_HD    ((size_t)2*CD*CB)
#define OFF_CDI  (OFF_HD + SZ_HD)
#define SZ_CDI   ((size_t)CD*CB)
#define SCRATCH_TOTAL (OFF_CDI + SZ_CDI)

// ---- fp16 scratch layout ----
#define HOFF_WIHF ((size_t)0)
#define HSZ_WIHF  ((size_t)4*CH*CE)
#define HOFF_WIHB (HOFF_WIHF + HSZ_WIHF)
#define HSZ_WIHB  ((size_t)4*CH*CE)
#define HOFF_WIHD (HOFF_WIHB + HSZ_WIHB)
#define HSZ_WIHD  ((size_t)4*CD*CE)
#define HOFF_WQ   (HOFF_WIHD + HSZ_WIHD)
#define HSZ_WQ    ((size_t)CD*CD)
#define HOFF_WK   (HOFF_WQ + HSZ_WQ)
#define HSZ_WK    ((size_t)CD*CD)
#define HOFF_WV   (HOFF_WK + HSZ_WK)
#define HSZ_WV    ((size_t)CD*CD)
#define HOFF_WFC  (HOFF_WV + HSZ_WV)
#define HSZ_WFC   ((size_t)CV*CD)
#define HOFF_XE   (HOFF_WFC + HSZ_WFC)
#define HSZ_XE    ((size_t)CB*CTE*CE)
#define HOFF_XD   (HOFF_XE + HSZ_XE)
#define HSZ_XD    ((size_t)CB*CTD*CE)
#define HOFF_DEC  (HOFF_XD + HSZ_XD)
#define HSZ_DEC   ((size_t)CB*CTD*CD)
#define HOFF_ENC  (HOFF_DEC + HSZ_DEC)
#define HSZ_ENC   ((size_t)CB*CTE*CD)
#define HOFF_LN   (HOFF_ENC + HSZ_ENC)
#define HSZ_LN    ((size_t)CB*CTD*CD)
#define HSCRATCH_TOTAL (HOFF_LN + HSZ_LN)

__device__ float  g_scratch[SCRATCH_TOTAL];
__device__ __half g_scratch_h[HSCRATCH_TOTAL];
__device__ unsigned g_bar_arrive[2 * 32];    // slot s at [s*32], own 128B line
__device__ unsigned g_bar_release[2 * 32];

__device__ __forceinline__ unsigned ld_acq_gpu(const unsigned* p) {
    unsigned v;
    asm volatile("ld.acquire.gpu.global.b32 %0, [%1];" : "=r"(v) : "l"(p) : "memory");
    return v;
}
__device__ __forceinline__ void st_rel_gpu(unsigned* p, unsigned v) {
    asm volatile("st.release.gpu.global.b32 [%0], %1;" :: "l"(p), "r"(v) : "memory");
}
// R15-style atomic grid barrier, parametrized by slot (independent groups).
__device__ __forceinline__ void grid_sync_dev(int slot, unsigned nb) {
    __syncthreads();
    if (threadIdx.x == 0) {
        __threadfence();
        unsigned* arr = &g_bar_arrive[slot * 32];
        unsigned* rel = &g_bar_release[slot * 32];
        unsigned gen = ld_acq_gpu(rel);
        if (atomicAdd(arr, 1u) == nb - 1u) {
            *arr = 0u;
            st_rel_gpu(rel, gen + 1u);
        } else {
            while (ld_acq_gpu(rel) == gen) {}
        }
    }
    __syncthreads();
}

__device__ __forceinline__ float sigmoidf_(float x) { return 1.0f / (1.0f + expf(-x)); }

__device__ __forceinline__ uint32_t smem_u32(const void* p) {
    uint32_t a;
    asm("{ .reg .u64 t; cvta.to.shared.u64 t, %1; cvt.u32.u64 %0, t; }" : "=r"(a) : "l"(p));
    return a;
}
__device__ __forceinline__ void cp_async16(uint32_t dst, const void* src) {
    asm volatile("cp.async.cg.shared.global [%0], [%1], 16;" :: "r"(dst), "l"(src));
}
__device__ __forceinline__ void cp_commit() { asm volatile("cp.async.commit_group;" ::: "memory"); }

// ---- packed f32x2 helpers ----
__device__ __forceinline__ uint64_t pack2(float lo, float hi) {
    uint64_t r;
    asm("mov.b64 %0, {%1,%2};" : "=l"(r) : "f"(lo), "f"(hi));
    return r;
}
__device__ __forceinline__ void unpack2(uint64_t v, float& lo, float& hi) {
    asm("mov.b64 {%0,%1}, %2;" : "=f"(lo), "=f"(hi) : "l"(v));
}
__device__ __forceinline__ void fma2(uint64_t& acc, uint64_t a, uint64_t b) {
    asm("fma.rn.f32x2 %0, %1, %2, %0;" : "+l"(acc) : "l"(a), "l"(b));
}
__device__ __forceinline__ void add2(uint64_t& a, uint64_t b) {
    asm("add.rn.f32x2 %0, %0, %1;" : "+l"(a) : "l"(b));
}

__device__ __forceinline__ void mma_f16(float* c, const uint32_t* a, const uint32_t* b) {
    asm volatile(
        "mma.sync.aligned.m16n8k16.row.col.f32.f16.f16.f32 "
        "{%0,%1,%2,%3}, {%4,%5,%6,%7}, {%8,%9}, {%0,%1,%2,%3};"
        : "+f"(c[0]), "+f"(c[1]), "+f"(c[2]), "+f"(c[3])
        : "r"(a[0]), "r"(a[1]), "r"(a[2]), "r"(a[3]), "r"(b[0]), "r"(b[1]));
}
__device__ __forceinline__ uint32_t h2_bits(float lo, float hi) {
    __half2 h = __floats2half2_rn(lo, hi);
    return *(uint32_t*)&h;
}

// ---- fp32 -> fp16 array convert ----
__global__ void __launch_bounds__(256) cvt_fp16_kernel(
    const float* __restrict__ src, __half* __restrict__ dst)
{
    int i = blockIdx.x * 256 + threadIdx.x;
    float4 v = ((const float4*)src)[i];
    uint2 u = make_uint2(h2_bits(v.x, v.y), h2_bits(v.z, v.w));
    *(uint2*)(dst + (size_t)i * 4) = u;
}

// ===================== fp16 m16n8k16 GEMM, cp.async 3-stage =====================
// Split-bias: cols [0,Nsplit) use b1lo/b2lo at index cn; cols >= Nsplit use
// b1hi/b2hi at index cn-Nsplit. Pass Nsplit=N and duplicate ptrs for no split.
#define BM 128
#define BN 128
#define GBK 32
#define GST 3
#define PADH 40
#define TILE_HH (128 * PADH)
#define GEMM_SMEM (GST * 2 * TILE_HH * 2)    // 61440 B

__global__ void __launch_bounds__(256, 2) gemm_tc_kernel(
    const __half* __restrict__ A, const __half* __restrict__ W,
    const float* __restrict__ b1lo, const float* __restrict__ b2lo,
    const float* __restrict__ b1hi, const float* __restrict__ b2hi,
    float* __restrict__ C, int N, int K, int Nsplit)
{
    extern __shared__ __half hsm_g[];
    __half* sA = hsm_g;
    __half* sB = hsm_g + GST * TILE_HH;

    const int tid  = threadIdx.x;
    const int warp = tid >> 5;
    const int lane = tid & 31;
    const int g    = lane >> 2;
    const int tig  = lane & 3;
    const int wm   = warp >> 2;
    const int wn   = warp & 3;
    const int m0   = blockIdx.x * BM;
    const int n0   = blockIdx.y * BN;
    const int nst  = K / GBK;

    const uint32_t sA_u = smem_u32(sA);
    const uint32_t sB_u = smem_u32(sB);

    float acc[4][4][4];
#pragma unroll
    for (int i = 0; i < 4; i++)
#pragma unroll
        for (int j = 0; j < 4; j++)
#pragma unroll
            for (int r = 0; r < 4; r++) acc[i][j][r] = 0.0f;

    auto load_stage = [&](int kidx, int s) {
        const __half* Ag = A + (size_t)m0 * K + kidx * GBK;
        const __half* Wg = W + (size_t)n0 * K + kidx * GBK;
        uint32_t aB = sA_u + (uint32_t)(s * TILE_HH * 2);
        uint32_t bB = sB_u + (uint32_t)(s * TILE_HH * 2);
#pragma unroll
        for (int q = 0; q < 2; q++) {
            int ch = q * 256 + tid;
            int r = ch >> 2, c = ch & 3;
            cp_async16(aB + (uint32_t)(r * 80 + c * 16), Ag + (size_t)r * K + c * 8);
        }
#pragma unroll
        for (int q = 0; q < 2; q++) {
            int ch = q * 256 + tid;
            int r = ch >> 2, c = ch & 3;
            cp_async16(bB + (uint32_t)(r * 80 + c * 16), Wg + (size_t)r * K + c * 8);
        }
        cp_commit();
    };

    load_stage(0, 0);
    load_stage(1, 1);

    for (int i = 0; i < nst; i++) {
        if (i + 2 < nst) {
            load_stage(i + 2, (i + 2) % GST);
            asm volatile("cp.async.wait_group 2;" ::: "memory");
        } else if (i + 1 < nst) {
            asm volatile("cp.async.wait_group 1;" ::: "memory");
        } else {
            asm volatile("cp.async.wait_group 0;" ::: "memory");
        }
        __syncthreads();

        const int s = i % GST;
        const uint32_t* aS = (const uint32_t*)(sA + s * TILE_HH);
        const uint32_t* bS = (const uint32_t*)(sB + s * TILE_HH);

#pragma unroll
        for (int ks = 0; ks < 2; ks++) {
            const int u0 = ks * 8 + tig;
            uint32_t af[4][4], bf[4][2];
#pragma unroll
            for (int mt = 0; mt < 4; mt++) {
                int row = wm * 64 + mt * 16 + g;
                af[mt][0] = aS[row * 20 + u0];
                af[mt][1] = aS[(row + 8) * 20 + u0];
                af[mt][2] = aS[row * 20 + u0 + 4];
                af[mt][3] = aS[(row + 8) * 20 + u0 + 4];
            }
#pragma unroll
            for (int nt = 0; nt < 4; nt++) {
                int n = wn * 32 + nt * 8 + g;
                bf[nt][0] = bS[n * 20 + u0];
                bf[nt][1] = bS[n * 20 + u0 + 4];
            }
#pragma unroll
            for (int mt = 0; mt < 4; mt++)
#pragma unroll
                for (int nt = 0; nt < 4; nt++)
                    mma_f16(acc[mt][nt], af[mt], bf[nt]);
        }
        __syncthreads();
    }

#pragma unroll
    for (int nt = 0; nt < 4; nt++) {
        int cn = n0 + wn * 32 + nt * 8 + 2 * tig;
        int nn = cn;
        const float* B1 = b1lo;
        const float* B2 = b2lo;
        if (cn >= Nsplit) { nn = cn - Nsplit; B1 = b1hi; B2 = b2hi; }
        float b0 = B1 ? B1[nn] : 0.0f;
        float b1 = B1 ? B1[nn + 1] : 0.0f;
        if (B2) { b0 += B2[nn]; b1 += B2[nn + 1]; }
#pragma unroll
        for (int mt = 0; mt < 4; mt++) {
            int r = m0 + wm * 64 + mt * 16 + g;
            float2 o0 = make_float2(acc[mt][nt][0] + b0, acc[mt][nt][1] + b1);
            float2 o1 = make_float2(acc[mt][nt][2] + b0, acc[mt][nt][3] + b1);
            *(float2*)(C + (size_t)r * N + cn) = o0;
            *(float2*)(C + (size_t)(r + 8) * N + cn) = o1;
        }
    }
}

// ---- embedding gather -> fp16 ----
__global__ void __launch_bounds__(128) embed_kernel(
    const int* __restrict__ eseq, const int* __restrict__ dseq,
    const float* __restrict__ eemb, const float* __restrict__ demb,
    __half* __restrict__ xe, __half* __restrict__ xd)
{
    int r = blockIdx.x;
    int tid = threadIdx.x;
    if (r < CB * CTE) {
        int tok = eseq[r];
        float4 v = ((const float4*)(eemb + (size_t)tok * CE))[tid];
        ((uint2*)(xe + (size_t)r * CE))[tid] = make_uint2(h2_bits(v.x, v.y), h2_bits(v.z, v.w));
    } else {
        int r2 = r - CB * CTE;
        int tok = dseq[r2];
        float4 v = ((const float4*)(demb + (size_t)tok * CE))[tid];
        ((uint2*)(xd + (size_t)r2 * CE))[tid] = make_uint2(h2_bits(v.x, v.y), h2_bits(v.z, v.w));
    }
}

// ===================== encoder recurrence (1024 thr, k-pair, dir-split barrier) ==========
#define EW_STRIDE (4 * CH + 4)
#define HPAD_E    (CH + 4)
#define ENC_RED_F (8 * EW_STRIDE + CB * HPAD_E)
#define ENC_SMEM  (ENC_RED_F * 4 + 7 * 8 * 16 * 16)

__global__ void __launch_bounds__(1024) enc_rnn_kernel(
    const float* __restrict__ Whh_f, const float* __restrict__ Whh_b,
    const float* __restrict__ xgfb,                       // [row][8*CH] fused
    __half* __restrict__ ench, float* __restrict__ hebuf,
    float* __restrict__ hd0, float* __restrict__ cdi)
{
    extern __shared__ float sm[];
    float* wsm = sm;
    float* hsm = sm + 8 * EW_STRIDE;
    ulonglong2* red = (ulonglong2*)(sm + ENC_RED_F);

    const int tid = threadIdx.x;
    const int b = tid & 15, ul = (tid >> 4) & 7, qr = tid >> 7;
    const int dir = blockIdx.x >> 6;
    const int u = (blockIdx.x & 63) * 8 + ul;
    const int ubase = (blockIdx.x & 63) * 8;

    const float* Whh = dir ? Whh_b : Whh_f;
    const float* xg  = xgfb + dir * (4 * CH);

    for (int i = tid; i < 4096; i += 1024) {
        int ulw = i >> 9;
        int g = (i >> 7) & 3;
        int k4 = i & 127;
        float4 v = *(const float4*)(Whh + ((size_t)(g * CH + ubase + ulw)) * CH + k4 * 4);
        float* dst = wsm + ulw * EW_STRIDE + k4 * 16 + ((g & 2) << 1) + ((g & 1) << 1);
        dst[0] = v.x; dst[1] = v.y; dst[8] = v.z; dst[9] = v.w;
    }

    const ulonglong2* wq = (const ulonglong2*)(wsm + ul * EW_STRIDE) + qr * 64;
    const ulonglong2* hq = (const ulonglong2*)(hsm + b * HPAD_E) + qr * 16;

    float c = 0.0f, h = 0.0f;
    if (qr == 0)
        __stcg(&hebuf[((size_t)(0 * 2 + dir) * CB + b) * CH + u], 0.0f);
    grid_sync_dev(dir, 64);

    for (int t = 0; t < CTE; t++) {
        const int cur = t & 1;
        {
            const float4* src = (const float4*)(hebuf + (size_t)(cur * 2 + dir) * (CB * CH));
            for (int i = tid; i < CB * CH / 4; i += 1024) {
                int bb = i >> 7, k4 = i & 127;
                *(float4*)(hsm + bb * HPAD_E + k4 * 4) = __ldcg(&src[i]);
            }
        }
        __syncthreads();

        const int te = dir ? (CTE - 1 - t) : t;
        float xgi = 0, xgf2 = 0, xgg = 0, xgo = 0;
        if (qr == 0) {
            size_t xb = ((size_t)(b * CTE + te)) * (8 * CH) + u;
            xgi = xg[xb]; xgf2 = xg[xb + CH];
            xgg = xg[xb + 2 * CH]; xgo = xg[xb + 3 * CH];
        }

        uint64_t ai = 0, af = 0, ag = 0, ao = 0;
#pragma unroll 4
        for (int k4 = 0; k4 < 16; k4++) {
            ulonglong2 hh = hq[k4];
            ulonglong2 w0 = wq[k4 * 4 + 0];
            ulonglong2 w1 = wq[k4 * 4 + 1];
            ulonglong2 w2 = wq[k4 * 4 + 2];
            ulonglong2 w3 = wq[k4 * 4 + 3];
            fma2(ai, w0.x, hh.x); fma2(af, w0.y, hh.x);
            fma2(ag, w1.x, hh.x); fma2(ao, w1.y, hh.x);
            fma2(ai, w2.x, hh.y); fma2(af, w2.y, hh.y);
            fma2(ag, w3.x, hh.y); fma2(ao, w3.y, hh.y);
        }
        float ai_l, ai_h, af_l, af_h, ag_l, ag_h, ao_l, ao_h;
        unpack2(ai, ai_l, ai_h); unpack2(af, af_l, af_h);
        unpack2(ag, ag_l, ag_h); unpack2(ao, ao_l, ao_h);
        float si = ai_l + ai_h, sf = af_l + af_h;
        float sg = ag_l + ag_h, so = ao_l + ao_h;

        if (qr) {
            ulonglong2 r; r.x = pack2(si, sf); r.y = pack2(sg, so);
            red[((qr - 1) * 8 + ul) * 16 + b] = r;
        }
        __syncthreads();
        if (qr == 0) {
            uint64_t p0 = pack2(si + xgi, sf + xgf2);
            uint64_t p1 = pack2(sg + xgg, so + xgo);
#pragma unroll
            for (int q = 0; q < 7; q++) {
                ulonglong2 r = red[(q * 8 + ul) * 16 + b];
                add2(p0, r.x);
                add2(p1, r.y);
            }
            float vi, vf, vg, vo;
            unpack2(p0, vi, vf);
            unpack2(p1, vg, vo);
            float ig = sigmoidf_(vi), fg = sigmoidf_(vf);
            float gg = tanhf(vg),     og = sigmoidf_(vo);
            c = fg * c + ig * gg;
            h = og * tanhf(c);

            __stcg(&hebuf[((size_t)((cur ^ 1) * 2 + dir) * CB + b) * CH + u], h);
            ench[((size_t)(b * CTE + te)) * CD + dir * CH + u] = __float2half(h);
        }
        if (t + 1 < CTE) grid_sync_dev(dir, 64);
    }

    if (qr == 0) {
        __stcg(&hd0[(size_t)b * CD + dir * CH + u], h);
        __stcg(&cdi[(size_t)b * CD + dir * CH + u], c);
    }
}

// ===================== decoder recurrence (1024 thr, k-pair scheme) =====================
#define DW_STRIDE (4 * CD + 4)
#define HPAD_D    (CD + 4)
#define DEC_RED_F (8 * DW_STRIDE + CB * HPAD_D)
#define DEC_SMEM  (DEC_RED_F * 4 + 7 * 8 * 16 * 16)

__global__ void __launch_bounds__(1024) dec_rnn_kernel(
    const float* __restrict__ Whh, const float* __restrict__ xg,
    float* __restrict__ dec, __half* __restrict__ dech,
    float* __restrict__ hbuf, const float* __restrict__ cinit)
{
    extern __shared__ float sm[];
    float* wsm = sm;
    float* hsm = sm + 8 * DW_STRIDE;
    ulonglong2* red = (ulonglong2*)(sm + DEC_RED_F);

    const int tid = threadIdx.x;
    const int b = tid & 15, ul = (tid >> 4) & 7, qr = tid >> 7;
    const int u = blockIdx.x * 8 + ul;
    const int ubase = blockIdx.x * 8;

    for (int i = tid; i < 8192; i += 1024) {
        int ulw = i >> 10;
        int g = (i >> 8) & 3;
        int k4 = i & 255;
        float4 v = *(const float4*)(Whh + ((size_t)(g * CD + ubase + ulw)) * CD + k4 * 4);
        float* dst = wsm + ulw * DW_STRIDE + k4 * 16 + ((g & 2) << 1) + ((g & 1) << 1);
        dst[0] = v.x; dst[1] = v.y; dst[8] = v.z; dst[9] = v.w;
    }

    const ulonglong2* wq = (const ulonglong2*)(wsm + ul * DW_STRIDE) + qr * 128;
    const ulonglong2* hq = (const ulonglong2*)(hsm + b * HPAD_D) + qr * 32;

    float c = (qr == 0) ? __ldcg(&cinit[(size_t)b * CD + u]) : 0.0f;

    for (int t = 0; t < CTD; t++) {
        const int cur = t & 1;
        {
            const float4* src = (const float4*)(hbuf + (size_t)cur * (CB * CD));
            for (int i = tid; i < CB * CD / 4; i += 1024) {
                int bb = i >> 8, k4 = i & 255;
                *(float4*)(hsm + bb * HPAD_D + k4 * 4) = __ldcg(&src[i]);
            }
        }
        __syncthreads();

        float xgi = 0, xgf2 = 0, xgg = 0, xgo = 0;
        if (qr == 0) {
            size_t xb = ((size_t)(b * CTD + t)) * (4 * CD) + u;
            xgi = xg[xb]; xgf2 = xg[xb + CD];
            xgg = xg[xb + 2 * CD]; xgo = xg[xb + 3 * CD];
        }

        uint64_t ai = 0, af = 0, ag = 0, ao = 0;
#pragma unroll 4
        for (int k4 = 0; k4 < 32; k4++) {
            ulonglong2 hh = hq[k4];
            ulonglong2 w0 = wq[k4 * 4 + 0];
            ulonglong2 w1 = wq[k4 * 4 + 1];
            ulonglong2 w2 = wq[k4 * 4 + 2];
            ulonglong2 w3 = wq[k4 * 4 + 3];
            fma2(ai, w0.x, hh.x); fma2(af, w0.y, hh.x);
            fma2(ag, w1.x, hh.x); fma2(ao, w1.y, hh.x);
            fma2(ai, w2.x, hh.y); fma2(af, w2.y, hh.y);
            fma2(ag, w3.x, hh.y); fma2(ao, w3.y, hh.y);
        }
        float ai_l, ai_h, af_l, af_h, ag_l, ag_h, ao_l, ao_h;
        unpack2(ai, ai_l, ai_h); unpack2(af, af_l, af_h);
        unpack2(ag, ag_l, ag_h); unpack2(ao, ao_l, ao_h);
        float si = ai_l + ai_h, sf = af_l + af_h;
        float sg = ag_l + ag_h, so = ao_l + ao_h;

        if (qr) {
            ulonglong2 r; r.x = pack2(si, sf); r.y = pack2(sg, so);
            red[((qr - 1) * 8 + ul) * 16 + b] = r;
        }
        __syncthreads();
        if (qr == 0) {
            uint64_t p0 = pack2(si + xgi, sf + xgf2);
            uint64_t p1 = pack2(sg + xgg, so + xgo);
#pragma unroll
            for (int q = 0; q < 7; q++) {
                ulonglong2 r = red[(q * 8 + ul) * 16 + b];
                add2(p0, r.x);
                add2(p1, r.y);
            }
            float vi, vf, vg, vo;
            unpack2(p0, vi, vf);
            unpack2(p1, vg, vo);
            float ig = sigmoidf_(vi), fg = sigmoidf_(vf);
            float gg = tanhf(vg),     og = sigmoidf_(vo);
            c = fg * c + ig * gg;
            float h = og * tanhf(c);

            __stcg(&hbuf[(size_t)(cur ^ 1) * (CB * CD) + (size_t)b * CD + u], h);
            dec[((size_t)(b * CTD + t)) * CD + u] = h;
            dech[((size_t)(b * CTD + t)) * CD + u] = __float2half(h);
        }
        if (t + 1 < CTD) grid_sync_dev(0, 128);
    }
}

// ===================== attention v2 on fused kv [row][2048] =====================
#define ATTN_SMEM ((16 * 1024 + 16 * 132 + 16 * 1024) * 4)

__global__ void __launch_bounds__(256) attn_kernel(
    const int* __restrict__ eseq,
    const float* __restrict__ q, const float* __restrict__ kv,
    float* __restrict__ ctx)
{
    extern __shared__ float asmem[];
    float* qs  = asmem;
    float* att = qs + 16 * 1024;
    float* vs  = att + 16 * 132;

    const int tid = threadIdx.x;
    const int b   = blockIdx.x >> 3;
    const int qt0 = (blockIdx.x & 7) * 16;

    for (int i = tid; i < 4096; i += 256) {
        int row = i >> 8, c = i & 255;
        ((float4*)(qs + row * 1024))[c] =
            ((const float4*)(q + ((size_t)(b * CTD + qt0 + row)) * CD))[c];
    }
    __syncthreads();

    {
        const int qh = tid >> 7, kt = tid & 127;
        float s[8] = {0, 0, 0, 0, 0, 0, 0, 0};
        const float4* kr = (const float4*)(kv + ((size_t)(b * CTE + kt)) * (2 * CD));
#pragma unroll 4
        for (int k4 = 0; k4 < 256; k4++) {
            float4 kvv = kr[k4];
#pragma unroll
            for (int j = 0; j < 8; j++) {
                float4 q4 = ((const float4*)(qs + (qh * 8 + j) * 1024))[k4];
                s[j] = fmaf(q4.x, kvv.x, s[j]);
                s[j] = fmaf(q4.y, kvv.y, s[j]);
                s[j] = fmaf(q4.z, kvv.z, s[j]);
                s[j] = fmaf(q4.w, kvv.w, s[j]);
            }
        }
        bool pad = (eseq[b * CTE + kt] == 0);
#pragma unroll
        for (int j = 0; j < 8; j++)
            att[(qh * 8 + j) * 132 + kt] = pad ? -1e30f : s[j] * 0.03125f;
    }
    __syncthreads();

    {
        const int w = tid >> 5, lane = tid & 31;
#pragma unroll
        for (int rr = 0; rr < 2; rr++) {
            int r = w * 2 + rr;
            float m = -1e30f;
#pragma unroll
            for (int c = lane; c < 128; c += 32) m = fmaxf(m, att[r * 132 + c]);
#pragma unroll
            for (int o = 16; o > 0; o >>= 1) m = fmaxf(m, __shfl_xor_sync(0xffffffffu, m, o));
            float sum = 0.0f;
#pragma unroll
            for (int c = lane; c < 128; c += 32) {
                float e = expf(att[r * 132 + c] - m);
                att[r * 132 + c] = e;
                sum += e;
            }
#pragma unroll
            for (int o = 16; o > 0; o >>= 1) sum += __shfl_xor_sync(0xffffffffu, sum, o);
            float inv = 1.0f / sum;
#pragma unroll
            for (int c = lane; c < 128; c += 32) att[r * 132 + c] *= inv;
        }
    }
    __syncthreads();

    {
        const int qt_l = tid >> 4, ds = tid & 15;
        float4 acc[16];
#pragma unroll
        for (int j = 0; j < 16; j++) acc[j] = make_float4(0, 0, 0, 0);

        for (int chunk = 0; chunk < 8; chunk++) {
            for (int i = tid; i < 4096; i += 256) {
                int row = i >> 8, c = i & 255;
                ((float4*)(vs + row * 1024))[c] =
                    ((const float4*)(kv + ((size_t)(b * CTE + chunk * 16 + row)) * (2 * CD) + CD))[c];
            }
            __syncthreads();
#pragma unroll 2
            for (int r = 0; r < 16; r++) {
                float a = att[qt_l * 132 + chunk * 16 + r];
                const float4* vr = (const float4*)(vs + r * 1024) + ds;
#pragma unroll
                for (int j = 0; j < 16; j++) {
                    float4 vv = vr[j * 16];
                    acc[j].x = fmaf(a, vv.x, acc[j].x);
                    acc[j].y = fmaf(a, vv.y, acc[j].y);
                    acc[j].z = fmaf(a, vv.z, acc[j].z);
                    acc[j].w = fmaf(a, vv.w, acc[j].w);
                }
            }
            __syncthreads();
        }

        float4* cr = (float4*)(ctx + ((size_t)(b * CTD + qt0 + qt_l)) * CD) + ds;
#pragma unroll
        for (int j = 0; j < 16; j++) cr[j * 16] = acc[j];
    }
}

// ---- tanh(dec + ctx) -> layernorm -> fp16 ----
__global__ void __launch_bounds__(256) tanh_ln_kernel(
    const float* __restrict__ dec, const float* __restrict__ ctx,
    const float* __restrict__ gamma, const float* __restrict__ beta,
    __half* __restrict__ lnh)
{
    __shared__ float rs[8], rss[8];
    const int tid = threadIdx.x;
    const int row = blockIdx.x;
    const float4 a = ((const float4*)(dec + (size_t)row * CD))[tid];
    const float4 b = ((const float4*)(ctx + (size_t)row * CD))[tid];
    float t0 = tanhf(a.x + b.x), t1 = tanhf(a.y + b.y);
    float t2 = tanhf(a.z + b.z), t3 = tanhf(a.w + b.w);
    float s = t0 + t1 + t2 + t3;
    float ss = t0*t0 + t1*t1 + t2*t2 + t3*t3;
#pragma unroll
    for (int o = 16; o > 0; o >>= 1) {
        s  += __shfl_xor_sync(0xffffffffu, s, o);
        ss += __shfl_xor_sync(0xffffffffu, ss, o);
    }
    if ((tid & 31) == 0) { rs[tid >> 5] = s; rss[tid >> 5] = ss; }
    __syncthreads();
    if (tid < 8) { s = rs[tid]; ss = rss[tid]; }
    else { s = 0; ss = 0; }
    if (tid < 32) {
#pragma unroll
        for (int o = 4; o > 0; o >>= 1) {
            s  += __shfl_xor_sync(0xffffffffu, s, o);
            ss += __shfl_xor_sync(0xffffffffu, ss, o);
        }
        if (tid == 0) { rs[0] = s; rss[0] = ss; }
    }
    __syncthreads();
    float mu = rs[0] * (1.0f / CD);
    float var = rss[0] * (1.0f / CD) - mu * mu;
    float rstd = rsqrtf(var + 1e-5f);
    const float4 g = ((const float4*)gamma)[tid];
    const float4 be = ((const float4*)beta)[tid];
    float o0 = (t0 - mu) * rstd * g.x + be.x;
    float o1 = (t1 - mu) * rstd * g.y + be.y;
    float o2 = (t2 - mu) * rstd * g.z + be.z;
    float o3 = (t3 - mu) * rstd * g.w + be.w;
    ((uint2*)(lnh + (size_t)row * CD))[tid] = make_uint2(h2_bits(o0, o1), h2_bits(o2, o3));
}

extern "C" void kernel_launch(void* const* d_in, const int* in_sizes, int n_in,
                              void* d_out, int out_size) {
    const int*   eseq  = (const int*)d_in[0];
    const int*   dseq  = (const int*)d_in[1];
    const float* eemb  = (const float*)d_in[2];
    const float* demb  = (const float*)d_in[3];
    const float* Wih_f = (const float*)d_in[4];
    const float* Whh_f = (const float*)d_in[5];
    const float* bih_f = (const float*)d_in[6];
    const float* bhh_f = (const float*)d_in[7];
    const float* Wih_b = (const float*)d_in[8];
    const float* Whh_b = (const float*)d_in[9];
    const float* bih_b = (const float*)d_in[10];
    const float* bhh_b = (const float*)d_in[11];
    const float* Wih_d = (const float*)d_in[12];
    const float* Whh_d = (const float*)d_in[13];
    const float* bih_d = (const float*)d_in[14];
    const float* bhh_d = (const float*)d_in[15];
    const float* Wq = (const float*)d_in[16];
    const float* bq = (const float*)d_in[17];
    const float* Wk = (const float*)d_in[18];
    const float* bk = (const float*)d_in[19];
    const float* Wv = (const float*)d_in[20];
    const float* bv = (const float*)d_in[21];
    const float* Wfc = (const float*)d_in[22];
    const float* bfc = (const float*)d_in[23];
    const float* gamma = (const float*)d_in[24];
    const float* beta  = (const float*)d_in[25];
    float* out = (float*)d_out;

    float* S = nullptr;
    cudaGetSymbolAddress((void**)&S, g_scratch);
    __half* H = nullptr;
    cudaGetSymbolAddress((void**)&H, g_scratch_h);

    float* xgfb = S + OFF_XGFB;
    float* xgd  = S + OFF_XGD;
    float* dec  = S + OFF_DEC;
    float* q    = S + OFF_Q;
    float* kv   = S + OFF_KV;
    float* ctx  = S + OFF_CTX;
    float* heb  = S + OFF_HE;
    float* hdb  = S + OFF_HD;
    float* cdi  = S + OFF_CDI;

    __half* wihf_h = H + HOFF_WIHF;       // wihf|wihb contiguous
    __half* wihd_h = H + HOFF_WIHD;
    __half* wq_h   = H + HOFF_WQ;
    __half* wk_h   = H + HOFF_WK;         // wk|wv contiguous
    __half* wv_h   = H + HOFF_WV;
    __half* wihb_h = H + HOFF_WIHB;
    __half* wfc_h  = H + HOFF_WFC;
    __half* xe_h   = H + HOFF_XE;
    __half* xd_h   = H + HOFF_XD;
    __half* dec_h  = H + HOFF_DEC;
    __half* enc_h  = H + HOFF_ENC;
    __half* ln_h   = H + HOFF_LN;

    cudaFuncSetAttribute(enc_rnn_kernel,
                         cudaFuncAttributeMaxDynamicSharedMemorySize, ENC_SMEM);
    cudaFuncSetAttribute(dec_rnn_kernel,
                         cudaFuncAttributeMaxDynamicSharedMemorySize, DEC_SMEM);
    cudaFuncSetAttribute(gemm_tc_kernel,
                         cudaFuncAttributeMaxDynamicSharedMemorySize, GEMM_SMEM);
    cudaFuncSetAttribute(attn_kernel,
                         cudaFuncAttributeMaxDynamicSharedMemorySize, ATTN_SMEM);

    const int M = CB * CTE;  // 2048 (== CB*CTD)

    embed_kernel<<<CB * CTE + CB * CTD, 128>>>(eseq, dseq, eemb, demb, xe_h, xd_h);
    cvt_fp16_kernel<<<(int)(HSZ_WIHF/1024), 256>>>(Wih_f, wihf_h);
    cvt_fp16_kernel<<<(int)(HSZ_WIHB/1024), 256>>>(Wih_b, wihb_h);
    // fused xgf|xgb GEMM: N=4096, split bias at 2048
    gemm_tc_kernel<<<dim3(M/BM, 8*CH/BN), 256, GEMM_SMEM>>>(
        xe_h, wihf_h, bih_f, bhh_f, bih_b, bhh_b, xgfb, 8*CH, CE, 4*CH);
    cvt_fp16_kernel<<<(int)(HSZ_WIHD/1024), 256>>>(Wih_d, wihd_h);
    gemm_tc_kernel<<<dim3(M/BM, 4*CD/BN), 256, GEMM_SMEM>>>(
        xd_h, wihd_h, bih_d, bhh_d, bih_d, bhh_d, xgd, 4*CD, CE, 4*CD);

    enc_rnn_kernel<<<128, 1024, ENC_SMEM>>>(Whh_f, Whh_b, xgfb, enc_h, heb, hdb, cdi);
    dec_rnn_kernel<<<128, 1024, DEC_SMEM>>>(Whh_d, xgd, dec, dec_h, hdb, cdi);

    cvt_fp16_kernel<<<(int)(HSZ_WQ/1024), 256>>>(Wq, wq_h);
    cvt_fp16_kernel<<<(int)(HSZ_WK/1024), 256>>>(Wk, wk_h);
    cvt_fp16_kernel<<<(int)(HSZ_WV/1024), 256>>>(Wv, wv_h);
    gemm_tc_kernel<<<dim3(M/BM, CD/BN), 256, GEMM_SMEM>>>(
        dec_h, wq_h, bq, nullptr, bq, nullptr, q, CD, CD, CD);
    // fused k|v GEMM: N=2048, split bias at 1024
    gemm_tc_kernel<<<dim3(M/BM, 2*CD/BN), 256, GEMM_SMEM>>>(
        enc_h, wk_h, bk, nullptr, bv, nullptr, kv, 2*CD, CD, CD);

    attn_kernel<<<CB * 8, 256, ATTN_SMEM>>>(eseq, q, kv, ctx);
    tanh_ln_kernel<<<CB * CTD, 256>>>(dec, ctx, gamma, beta, ln_h);

    cvt_fp16_kernel<<<(int)(HSZ_WFC/1024), 256>>>(Wfc, wfc_h);
    gemm_tc_kernel<<<dim3(M/BM, CV/BN), 256, GEMM_SMEM>>>(
        ln_h, wfc_h, bfc, nullptr, bfc, nullptr, out, CV, CD, CV);
}